// round 12
// baseline (speedup 1.0000x reference)
#include <cuda_runtime.h>

// Problem constants: SCALE=64, B=4, P=S2=4096.
// Inputs (metadata order): corr_m (B,S2,S2) f32, gt_flow (B,2,64,64) f32,
//                          vis_mask (B,1,64,64) f32 [UNUSED],
//                          scale_ref (B,3,64,64) f32
// Output: concat(warp_smpl (B,3,64,64), warp_corr (B,3,64,64)) f32
//
// FINAL KERNEL (R1 artifact; best observed draw 6.37us over 11 benches of 9
// distinct variants). Workload is launch/replay-overhead bound: every pipe
// <1% busy, DRAM ~9%, and byte-identical code drew 6.37/6.62/6.88us across
// runs. Body = two irreducible data-dependent round trips (gt load -> idx
// math -> 16-way scattered gather -> FMA -> store). 32 regs, no smem,
// 128 blocks x 128 threads, one wave, max warp-level gather parallelism.

#define SC    64
#define S2    4096   // SC*SC
#define BATCH 4

__global__ __launch_bounds__(128)
void smpl_loss_pixel_kernel(const float* __restrict__ corr,
                            const float* __restrict__ gt,
                            const float* __restrict__ ref,
                            float* __restrict__ out)
{
    const int t = blockIdx.x * blockDim.x + threadIdx.x;
    if (t >= BATCH * S2) return;
    const int b = t >> 12;       // t / 4096
    const int p = t & (S2 - 1);  // t % 4096

    // gt_flow: (B, 2, 64, 64) -> gx from channel 0, gy from channel 1
    const float gx = (gt[(b * 2 + 0) * S2 + p] + 1.0f) * ((SC - 1) * 0.5f);
    const float gy = (gt[(b * 2 + 1) * S2 + p] + 1.0f) * ((SC - 1) * 0.5f);
    const float fx = floorf(gx);
    const float fy = floorf(gy);

    // clipped row/col coords (floats, matching reference clip-then-int32)
    const float r0 = fminf(fmaxf(fy,        0.0f), (float)(SC - 1));
    const float r1 = fminf(fmaxf(fy + 1.0f, 0.0f), (float)(SC - 1));
    const float c0 = fminf(fmaxf(fx,        0.0f), (float)(SC - 1));
    const float c1 = fminf(fmaxf(fx + 1.0f, 0.0f), (float)(SC - 1));

    int idx[4];
    idx[0] = (int)(r0 * (float)SC + c0);
    idx[1] = (int)(r0 * (float)SC + c1);
    idx[2] = (int)(r1 * (float)SC + c0);
    idx[3] = (int)(r1 * (float)SC + c1);

    const float wy0 = fy + 1.0f - gy;
    const float wy1 = gy - fy;
    const float wx0 = fx + 1.0f - gx;
    const float wx1 = gx - fx;
    float wgt[4];
    wgt[0] = wy0 * wx0;
    wgt[1] = wy0 * wx1;
    wgt[2] = wy1 * wx0;
    wgt[3] = wy1 * wx1;

    // Scatter-set semantics of the reference: for duplicate idx values
    // (possible only under coordinate clipping) the LAST offset wins, and the
    // duplicated index contributes exactly once to the einsum.
    // keep[i] = (no j > i has idx[j] == idx[i])
    bool keep[4];
#pragma unroll
    for (int i = 0; i < 4; i++) {
        keep[i] = true;
#pragma unroll
        for (int j = i + 1; j < 4; j++)
            if (idx[j] == idx[i]) keep[i] = false;
    }

    // Issue all loads up front for max MLP (each is independent).
    const float* __restrict__ crow = corr + ((size_t)b * S2 + (size_t)p) * S2;
    const float* __restrict__ rb0  = ref + (size_t)b * 3 * S2;
    const float* __restrict__ rb1  = rb0 + S2;
    const float* __restrict__ rb2  = rb0 + 2 * S2;

    float cv[4], rv0[4], rv1[4], rv2[4];
#pragma unroll
    for (int i = 0; i < 4; i++) {
        const int id = idx[i];
        cv[i]  = __ldg(crow + id);
        rv0[i] = __ldg(rb0 + id);
        rv1[i] = __ldg(rb1 + id);
        rv2[i] = __ldg(rb2 + id);
    }

    float s0 = 0.f, s1 = 0.f, s2 = 0.f;   // warp_smpl accumulators (c=0..2)
    float q0 = 0.f, q1 = 0.f, q2 = 0.f;   // warp_corr accumulators
#pragma unroll
    for (int i = 0; i < 4; i++) {
        if (!keep[i]) continue;
        const float wv = wgt[i];
        const float cc = cv[i];
        s0 = fmaf(wv, rv0[i], s0);
        s1 = fmaf(wv, rv1[i], s1);
        s2 = fmaf(wv, rv2[i], s2);
        q0 = fmaf(cc, rv0[i], q0);
        q1 = fmaf(cc, rv1[i], q1);
        q2 = fmaf(cc, rv2[i], q2);
    }

    // Output: warp_smpl first (B*3*S2 floats), then warp_corr.
    const size_t base = ((size_t)b * 3) * S2 + (size_t)p;
    out[base         ] = s0;
    out[base +     S2] = s1;
    out[base + 2 * S2] = s2;
    float* __restrict__ oc = out + (size_t)BATCH * 3 * S2;
    oc[base         ] = q0;
    oc[base +     S2] = q1;
    oc[base + 2 * S2] = q2;
}

extern "C" void kernel_launch(void* const* d_in, const int* in_sizes, int n_in,
                              void* d_out, int out_size)
{
    const float* corr = (const float*)d_in[0];  // (4, 4096, 4096)
    const float* gt   = (const float*)d_in[1];  // (4, 2, 64, 64)
    // d_in[2] = vis_mask, unused
    const float* ref  = (const float*)d_in[3];  // (4, 3, 64, 64)
    float* out = (float*)d_out;                 // 2 * 4 * 3 * 4096 floats

    const int total = BATCH * S2;               // 16384 threads
    const int threads = 128;
    const int blocks = (total + threads - 1) / threads;  // 128 blocks
    smpl_loss_pixel_kernel<<<blocks, threads>>>(corr, gt, ref, out);
}

// round 13
// speedup vs baseline: 1.4359x; 1.4359x over previous
#include <cuda_runtime.h>

// Problem constants: SCALE=64, B=4, P=S2=4096.
// Inputs (metadata order): corr_m (B,S2,S2) f32, gt_flow (B,2,64,64) f32,
//                          vis_mask (B,1,64,64) f32 [UNUSED],
//                          scale_ref (B,3,64,64) f32
// Output: concat(warp_smpl (B,3,64,64), warp_corr (B,3,64,64)) f32
//
// FINAL KERNEL (R1 artifact). Best observed draw 6.37us; byte-identical
// code has drawn 6.37/6.62/6.88/8.96us across runs -> bench noise dwarfs
// any structural lever. Workload is launch/replay-overhead bound: every
// pipe <1% busy, DRAM ~9%. Body = two irreducible data-dependent round
// trips (gt load -> idx math -> 16-way scattered gather -> FMA -> store).
// 32 regs, no smem, 128 blocks x 128 threads, one wave.

#define SC    64
#define S2    4096   // SC*SC
#define BATCH 4

__global__ __launch_bounds__(128)
void smpl_loss_pixel_kernel(const float* __restrict__ corr,
                            const float* __restrict__ gt,
                            const float* __restrict__ ref,
                            float* __restrict__ out)
{
    const int t = blockIdx.x * blockDim.x + threadIdx.x;
    if (t >= BATCH * S2) return;
    const int b = t >> 12;       // t / 4096
    const int p = t & (S2 - 1);  // t % 4096

    // gt_flow: (B, 2, 64, 64) -> gx from channel 0, gy from channel 1
    const float gx = (gt[(b * 2 + 0) * S2 + p] + 1.0f) * ((SC - 1) * 0.5f);
    const float gy = (gt[(b * 2 + 1) * S2 + p] + 1.0f) * ((SC - 1) * 0.5f);
    const float fx = floorf(gx);
    const float fy = floorf(gy);

    // clipped row/col coords (floats, matching reference clip-then-int32)
    const float r0 = fminf(fmaxf(fy,        0.0f), (float)(SC - 1));
    const float r1 = fminf(fmaxf(fy + 1.0f, 0.0f), (float)(SC - 1));
    const float c0 = fminf(fmaxf(fx,        0.0f), (float)(SC - 1));
    const float c1 = fminf(fmaxf(fx + 1.0f, 0.0f), (float)(SC - 1));

    int idx[4];
    idx[0] = (int)(r0 * (float)SC + c0);
    idx[1] = (int)(r0 * (float)SC + c1);
    idx[2] = (int)(r1 * (float)SC + c0);
    idx[3] = (int)(r1 * (float)SC + c1);

    const float wy0 = fy + 1.0f - gy;
    const float wy1 = gy - fy;
    const float wx0 = fx + 1.0f - gx;
    const float wx1 = gx - fx;
    float wgt[4];
    wgt[0] = wy0 * wx0;
    wgt[1] = wy0 * wx1;
    wgt[2] = wy1 * wx0;
    wgt[3] = wy1 * wx1;

    // Scatter-set semantics of the reference: for duplicate idx values
    // (possible only under coordinate clipping) the LAST offset wins, and the
    // duplicated index contributes exactly once to the einsum.
    // keep[i] = (no j > i has idx[j] == idx[i])
    bool keep[4];
#pragma unroll
    for (int i = 0; i < 4; i++) {
        keep[i] = true;
#pragma unroll
        for (int j = i + 1; j < 4; j++)
            if (idx[j] == idx[i]) keep[i] = false;
    }

    // Issue all loads up front for max MLP (each is independent).
    const float* __restrict__ crow = corr + ((size_t)b * S2 + (size_t)p) * S2;
    const float* __restrict__ rb0  = ref + (size_t)b * 3 * S2;
    const float* __restrict__ rb1  = rb0 + S2;
    const float* __restrict__ rb2  = rb0 + 2 * S2;

    float cv[4], rv0[4], rv1[4], rv2[4];
#pragma unroll
    for (int i = 0; i < 4; i++) {
        const int id = idx[i];
        cv[i]  = __ldg(crow + id);
        rv0[i] = __ldg(rb0 + id);
        rv1[i] = __ldg(rb1 + id);
        rv2[i] = __ldg(rb2 + id);
    }

    float s0 = 0.f, s1 = 0.f, s2 = 0.f;   // warp_smpl accumulators (c=0..2)
    float q0 = 0.f, q1 = 0.f, q2 = 0.f;   // warp_corr accumulators
#pragma unroll
    for (int i = 0; i < 4; i++) {
        if (!keep[i]) continue;
        const float wv = wgt[i];
        const float cc = cv[i];
        s0 = fmaf(wv, rv0[i], s0);
        s1 = fmaf(wv, rv1[i], s1);
        s2 = fmaf(wv, rv2[i], s2);
        q0 = fmaf(cc, rv0[i], q0);
        q1 = fmaf(cc, rv1[i], q1);
        q2 = fmaf(cc, rv2[i], q2);
    }

    // Output: warp_smpl first (B*3*S2 floats), then warp_corr.
    const size_t base = ((size_t)b * 3) * S2 + (size_t)p;
    out[base         ] = s0;
    out[base +     S2] = s1;
    out[base + 2 * S2] = s2;
    float* __restrict__ oc = out + (size_t)BATCH * 3 * S2;
    oc[base         ] = q0;
    oc[base +     S2] = q1;
    oc[base + 2 * S2] = q2;
}

extern "C" void kernel_launch(void* const* d_in, const int* in_sizes, int n_in,
                              void* d_out, int out_size)
{
    const float* corr = (const float*)d_in[0];  // (4, 4096, 4096)
    const float* gt   = (const float*)d_in[1];  // (4, 2, 64, 64)
    // d_in[2] = vis_mask, unused
    const float* ref  = (const float*)d_in[3];  // (4, 3, 64, 64)
    float* out = (float*)d_out;                 // 2 * 4 * 3 * 4096 floats

    const int total = BATCH * S2;               // 16384 threads
    const int threads = 128;
    const int blocks = (total + threads - 1) / threads;  // 128 blocks
    smpl_loss_pixel_kernel<<<blocks, threads>>>(corr, gt, ref, out);
}